// round 7
// baseline (speedup 1.0000x reference)
#include <cuda_runtime.h>
#include <cuda_bf16.h>
#include <cstddef>
#include <cstdint>

// Problem dims (fixed by the benchmark)
#define BB 128
#define TT 512
#define DD 512
#define UU 1024
#define GG 4096   // 4*U
#define OO 512
#define MM (BB * TT)   // 65536

#define NBLK 128        // persistent CTAs for scan

typedef __nv_bfloat16 bf16;

// ---------------- scratch (static device globals; no runtime allocation) ----
__device__ float g_xz[(size_t)MM * GG];        // [B*T][4U]
__device__ unsigned g_fc[16];                  // per-chunk producer epoch flags

// split-bf16 K-tripled operands:  A3=[Ah|Ah|Al], B3=[Bh|Bl|Bh]
__device__ bf16 g_a3x[(size_t)MM * 3 * DD];    // x        -> [M][1536]
__device__ bf16 g_a3h[(size_t)MM * 3 * UU];    // h states -> [M][3072] (written by scan)
__device__ bf16 g_b3k[(size_t)GG * 3 * DD];    // kernel^T -> [4096][1536]
__device__ bf16 g_b3w[(size_t)OO * 3 * UU];    // Wd^T     -> [512][3072]
__device__ bf16 g_h0[(size_t)BB * 3 * UU];     // h0 in [hi|hi|lo] layout

// ---------------- helpers ----------------------------------------------------
__device__ __forceinline__ float sigmoidf_(float x) { return 1.0f / (1.0f + __expf(-x)); }

__device__ __forceinline__ void cp16s(uint32_t daddr, const void* g) {
    asm volatile("cp.async.cg.shared.global [%0], [%1], 16;" :: "r"(daddr), "l"(g));
}
#define CP_COMMIT()  asm volatile("cp.async.commit_group;")
#define CP_WAIT(N)   asm volatile("cp.async.wait_group %0;" :: "n"(N))

__device__ __forceinline__ void ldsm_x4(uint32_t &r0, uint32_t &r1,
                                        uint32_t &r2, uint32_t &r3, uint32_t a) {
    asm volatile("ldmatrix.sync.aligned.m8n8.x4.shared.b16 {%0,%1,%2,%3}, [%4];"
                 : "=r"(r0), "=r"(r1), "=r"(r2), "=r"(r3) : "r"(a));
}
__device__ __forceinline__ void mma16816(float* d, const uint32_t* a,
                                         const uint32_t* b) {
    asm volatile(
        "mma.sync.aligned.m16n8k16.row.col.f32.bf16.bf16.f32 "
        "{%0,%1,%2,%3}, {%4,%5,%6,%7}, {%8,%9}, {%0,%1,%2,%3};"
        : "+f"(d[0]), "+f"(d[1]), "+f"(d[2]), "+f"(d[3])
        : "r"(a[0]), "r"(a[1]), "r"(a[2]), "r"(a[3]), "r"(b[0]), "r"(b[1]));
}
__device__ __forceinline__ uint32_t swz(uint32_t o) { return o ^ ((o >> 3) & 0x70); }
__device__ __forceinline__ uint32_t packbf(bf16 a, bf16 b) {
    uint16_t x = *(uint16_t*)&a, y = *(uint16_t*)&b;
    return (uint32_t)x | ((uint32_t)y << 16);
}
__device__ __forceinline__ void waitfc(int ck, unsigned target) {
    unsigned v;
    do {
        asm volatile("ld.global.acquire.gpu.u32 %0, [%1];"
                     : "=r"(v) : "l"(&g_fc[ck]) : "memory");
        if (v < target) __nanosleep(32);
    } while (v < target);
}

// ---------------- prep kernels ----------------------------------------------
__global__ __launch_bounds__(256) void init_state(const float* __restrict__ h0) {
    int i = blockIdx.x * 256 + threadIdx.x;   // covers 128*1024
    int b = i / UU, u = i % UU;
    float v = h0[i];
    bf16 h = __float2bfloat16(v);
    bf16 l = __float2bfloat16(v - __bfloat162float(h));
    bf16* o = g_h0 + (size_t)b * 3 * UU;
    o[u] = h; o[UU + u] = h; o[2 * UU + u] = l;
    if (i < 16) g_fc[i] = 0u;
}

// in [M][K] fp32 -> out [M][3K] bf16: [Ah | Ah | Al]
__global__ __launch_bounds__(256) void split_pack_rows(
    const float* __restrict__ in, bf16* __restrict__ out, int K) {
    size_t i = (size_t)blockIdx.x * 256 + threadIdx.x;
    int m = (int)(i / K), k = (int)(i % K);
    float v = in[i];
    bf16 h = __float2bfloat16(v);
    bf16 l = __float2bfloat16(v - __bfloat162float(h));
    bf16* o = out + (size_t)m * 3 * K;
    o[k] = h; o[K + k] = h; o[2 * K + k] = l;
}

// in [K][N] fp32 -> out [N][3K] bf16: [Bh | Bl | Bh]
__global__ __launch_bounds__(256) void split_pack_T(
    const float* __restrict__ in, bf16* __restrict__ out, int K, int N) {
    size_t i = (size_t)blockIdx.x * 256 + threadIdx.x;
    if (i >= (size_t)K * N) return;
    int k = (int)(i / N), n = (int)(i % N);
    float v = in[i];
    bf16 h = __float2bfloat16(v);
    bf16 l = __float2bfloat16(v - __bfloat162float(h));
    bf16* o = out + (size_t)n * 3 * K;
    o[k] = h; o[K + k] = l; o[2 * K + k] = h;
}

// ---------------- mma.sync bf16 GEMM (R5 two-stage config) ------------------
#define MMASM (2 * 32768)

__global__ __launch_bounds__(256, 1) void mma_gemm(
    const bf16* __restrict__ A3, const bf16* __restrict__ B3,
    const float* __restrict__ bias, float* __restrict__ C, int K3, int N) {
    extern __shared__ char smc[];
    const uint32_t sbase = (uint32_t)__cvta_generic_to_shared(smc);
    const int tid = threadIdx.x;
    const int wid = tid >> 5, lid = tid & 31;
    const int n0 = blockIdx.x * 128;
    const int m0 = blockIdx.y * 128;
    const int wm = (wid & 1) * 64;
    const int wn = (wid >> 1) * 32;
    const int nch = K3 / 64;

    float d[4][4][4];
#pragma unroll
    for (int i = 0; i < 4; i++)
#pragma unroll
        for (int j = 0; j < 4; j++)
#pragma unroll
            for (int q = 0; q < 4; q++) d[i][j][q] = 0.0f;

    auto load_chunk = [&](int buf, int k0) {
        uint32_t ab = sbase + buf * 32768;
        uint32_t bb = ab + 16384;
#pragma unroll
        for (int i = 0; i < 4; i++) {
            int e = tid + i * 256;
            int rr = e >> 3, c8 = e & 7;
            uint32_t off = swz((uint32_t)(rr * 128 + c8 * 16));
            cp16s(ab + off, A3 + (size_t)(m0 + rr) * K3 + k0 + c8 * 8);
            cp16s(bb + off, B3 + (size_t)(n0 + rr) * K3 + k0 + c8 * 8);
        }
    };

    load_chunk(0, 0);
    CP_COMMIT();

    int buf = 0;
    for (int c = 0; c < nch; c++) {
        if (c + 1 < nch) {
            load_chunk(buf ^ 1, (c + 1) * 64);
            CP_COMMIT();
            CP_WAIT(1);
        } else {
            CP_WAIT(0);
        }
        __syncthreads();

        const uint32_t ab = sbase + buf * 32768;
        const uint32_t bb = ab + 16384;
#pragma unroll
        for (int kk = 0; kk < 64; kk += 16) {
            uint32_t af[4][4];
#pragma unroll
            for (int mi = 0; mi < 4; mi++) {
                uint32_t off = (uint32_t)((wm + mi * 16 + (lid & 15)) * 128
                                          + kk * 2 + (lid >> 4) * 16);
                ldsm_x4(af[mi][0], af[mi][1], af[mi][2], af[mi][3], ab + swz(off));
            }
            uint32_t bf_[4][2];
#pragma unroll
            for (int ni = 0; ni < 2; ni++) {
                int sub = lid >> 3;
                uint32_t off = (uint32_t)((wn + ni * 16 + ((sub >> 1) & 1) * 8
                                           + (lid & 7)) * 128
                                          + kk * 2 + (sub & 1) * 16);
                ldsm_x4(bf_[ni * 2][0], bf_[ni * 2][1],
                        bf_[ni * 2 + 1][0], bf_[ni * 2 + 1][1], bb + swz(off));
            }
#pragma unroll
            for (int mi = 0; mi < 4; mi++)
#pragma unroll
                for (int nf = 0; nf < 4; nf++)
                    mma16816(d[mi][nf], af[mi], bf_[nf]);
        }
        __syncthreads();
        buf ^= 1;
    }

    const int lr = lid >> 2;
    const int lc = (lid & 3) * 2;
#pragma unroll
    for (int mi = 0; mi < 4; mi++) {
#pragma unroll
        for (int nf = 0; nf < 4; nf++) {
            int col = n0 + wn + nf * 8 + lc;
            float b0 = bias[col], b1 = bias[col + 1];
            int row0 = m0 + wm + mi * 16 + lr;
            float2 v0 = make_float2(d[mi][nf][0] + b0, d[mi][nf][1] + b1);
            float2 v1 = make_float2(d[mi][nf][2] + b0, d[mi][nf][3] + b1);
            *(float2*)&C[(size_t)row0 * N + col] = v0;
            *(float2*)&C[(size_t)(row0 + 8) * N + col] = v1;
        }
    }
}

// ---------------- persistent MMA LSTM scan (dataflow-synced) -----------------
// 128 CTAs. CTA g owns hidden cols [8g, 8g+8) x 4 gates (N=32, col n=gate*8+j).
// R slice resident in smem as split-bf16. Per step: 3-term HMMA.
// NO grid barrier: h history lives per-t in g_a3h (no anti-dependency), so
// chunk ck of h_{t-1} only needs its 8 producer CTAs done: fc[ck] >= 8t.
// Producer posts fence + atomicAdd(fc[g>>3]) after writing its h_t columns.
#define SC_RH 0
#define SC_RL 65536
#define SC_A  131072
#define SCANSM (SC_A + 3 * 32768)   // 229376

__global__ __launch_bounds__(256, 1) void lstm_scan_mma(
    const float* __restrict__ R, const float* __restrict__ c0in) {
    extern __shared__ char smc[];
    const uint32_t sb = (uint32_t)__cvta_generic_to_shared(smc);
    const int tid = threadIdx.x;
    const int wid = tid >> 5, lid = tid & 31;
    const int u0 = blockIdx.x * 8;
    const int wm = wid * 16;
    const int myflag = blockIdx.x >> 3;

    // ---- one-time: R slice -> smem split-bf16, swizzled chunks ----
    for (int e = tid; e < 32 * UU; e += 256) {
        int n = e & 31, k = e >> 5;
        int gate = n >> 3, j = n & 7;
        float v = R[(size_t)k * GG + gate * UU + u0 + j];
        bf16 h = __float2bfloat16(v);
        bf16 l = __float2bfloat16(v - __bfloat162float(h));
        uint32_t off = (uint32_t)((k >> 6) * 4096) + swz((uint32_t)(n * 128 + (k & 63) * 2));
        *(bf16*)(smc + SC_RH + off) = h;
        *(bf16*)(smc + SC_RL + off) = l;
    }

    // thread's (b,u) combos — fixed for the whole scan
    const int lr = lid >> 2, lc = (lid & 3) * 2;
    const int b1 = wm + lr, b2 = b1 + 8;
    const int bs_[4] = {b1, b1, b2, b2};
    const int uj_[4] = {lc, lc + 1, lc, lc + 1};

    float creg[4];
#pragma unroll
    for (int i = 0; i < 4; i++)
        creg[i] = c0in[(size_t)bs_[i] * UU + u0 + uj_[i]];

    __syncthreads();

    for (int t = 0; t < TT; t++) {
        // A source: h_{t-1} rows in [hi|hi|lo] layout
        const bf16* abase;
        size_t astride;
        if (t == 0) { abase = g_h0; astride = 3 * UU; }
        else        { abase = g_a3h + (size_t)(t - 1) * 3 * UU; astride = (size_t)TT * 3 * UU; }
        const unsigned tgt = 8u * (unsigned)t;

        auto loadA = [&](int buf, int ck) {
            uint32_t ah = sb + SC_A + buf * 32768;
            uint32_t al = ah + 16384;
#pragma unroll
            for (int i = 0; i < 4; i++) {
                int e = tid + i * 256;              // 0..1023
                int rr = e >> 3, c8 = e & 7;
                uint32_t off = swz((uint32_t)(rr * 128 + c8 * 16));
                const bf16* rowp = abase + (size_t)rr * astride + ck * 64 + c8 * 8;
                cp16s(ah + off, rowp);              // hi (cols 0..1023)
                cp16s(al + off, rowp + 2 * UU);     // lo (cols 2048..3071)
            }
        };

        // prologue: gate chunks 0,1 on their producers, then issue
        if (tid == 0 && t > 0) { waitfc(0, tgt); waitfc(1, tgt); }
        __syncthreads();
        loadA(0, 0);
        CP_COMMIT();
        loadA(1, 1);
        CP_COMMIT();

        // prefetch xz for this step (16 scattered LDG, hidden under MMA)
        float xzv[4][4];
#pragma unroll
        for (int i = 0; i < 4; i++) {
            const float* p = &g_xz[((size_t)bs_[i] * TT + t) * GG + u0 + uj_[i]];
#pragma unroll
            for (int g = 0; g < 4; g++) xzv[i][g] = p[(size_t)g * UU];
        }

        float d[4][4];
#pragma unroll
        for (int f = 0; f < 4; f++)
#pragma unroll
            for (int q = 0; q < 4; q++) d[f][q] = 0.0f;

        int buf = 0;
        for (int ck = 0; ck < 16; ck++) {
            if (ck < 15) { CP_WAIT(1); } else { CP_WAIT(0); }
            if (tid == 0 && t > 0 && ck + 2 < 16) waitfc(ck + 2, tgt);
            __syncthreads();
            if (ck + 2 < 16) {
                int bn = buf + 2; if (bn >= 3) bn -= 3;
                loadA(bn, ck + 2);
                CP_COMMIT();
            }

            const uint32_t ah = sb + SC_A + buf * 32768;
            const uint32_t al = ah + 16384;
            const uint32_t rh = sb + SC_RH + ck * 4096;
            const uint32_t rl = sb + SC_RL + ck * 4096;
#pragma unroll
            for (int kk = 0; kk < 64; kk += 16) {
                uint32_t offA = swz((uint32_t)((wm + (lid & 15)) * 128
                                               + kk * 2 + (lid >> 4) * 16));
                uint32_t afh[4], afl[4];
                ldsm_x4(afh[0], afh[1], afh[2], afh[3], ah + offA);
                ldsm_x4(afl[0], afl[1], afl[2], afl[3], al + offA);

                uint32_t bh[4][2], bl[4][2];
#pragma unroll
                for (int ni = 0; ni < 2; ni++) {
                    int sub = lid >> 3;
                    uint32_t offB = swz((uint32_t)((ni * 16 + ((sub >> 1) & 1) * 8
                                                    + (lid & 7)) * 128
                                                   + kk * 2 + (sub & 1) * 16));
                    ldsm_x4(bh[ni * 2][0], bh[ni * 2][1],
                            bh[ni * 2 + 1][0], bh[ni * 2 + 1][1], rh + offB);
                    ldsm_x4(bl[ni * 2][0], bl[ni * 2][1],
                            bl[ni * 2 + 1][0], bl[ni * 2 + 1][1], rl + offB);
                }
#pragma unroll
                for (int f = 0; f < 4; f++) {
                    mma16816(d[f], afh, bh[f]);
                    mma16816(d[f], afh, bl[f]);
                    mma16816(d[f], afl, bh[f]);
                }
            }
            buf = (buf == 2) ? 0 : buf + 1;
        }

        // gate update: d[f][i] = gate f for combo i  (col n = f*8 + j)
        float hn[4];
#pragma unroll
        for (int i = 0; i < 4; i++) {
            float zi = d[0][i] + xzv[i][0];
            float zf = d[1][i] + xzv[i][1];
            float zg = d[2][i] + xzv[i][2];
            float zo = d[3][i] + xzv[i][3];
            float ig = sigmoidf_(zi);
            float fg = sigmoidf_(zf);
            float og = sigmoidf_(zo);
            float gg = tanhf(zg);
            float cn = fg * creg[i] + ig * gg;
            creg[i] = cn;
            hn[i] = og * tanhf(cn);
        }

        // write h_t as [hi|hi|lo] pairs (combos 0,1 share row b1; 2,3 share b2)
#pragma unroll
        for (int pp = 0; pp < 2; pp++) {
            int b = pp ? b2 : b1;
            float v0 = hn[pp * 2], v1 = hn[pp * 2 + 1];
            bf16 h0b = __float2bfloat16(v0);
            bf16 h1b = __float2bfloat16(v1);
            bf16 l0b = __float2bfloat16(v0 - __bfloat162float(h0b));
            bf16 l1b = __float2bfloat16(v1 - __bfloat162float(h1b));
            uint32_t hp = packbf(h0b, h1b), lp = packbf(l0b, l1b);
            bf16* rowp = g_a3h + ((size_t)b * TT + t) * 3 * UU + u0 + lc;
            *(uint32_t*)(rowp)          = hp;
            *(uint32_t*)(rowp + UU)     = hp;
            *(uint32_t*)(rowp + 2 * UU) = lp;
        }

        // publish: this CTA's h_t columns are ready
        __syncthreads();
        if (tid == 0) {
            __threadfence();
            atomicAdd(&g_fc[myflag], 1u);
        }
    }
}

// ---------------- host launcher --------------------------------------------
extern "C" void kernel_launch(void* const* d_in, const int* in_sizes, int n_in,
                              void* d_out, int out_size) {
    const float* x      = (const float*)d_in[0];
    const float* h0     = (const float*)d_in[1];
    const float* c0in   = (const float*)d_in[2];
    const float* kernel = (const float*)d_in[3];
    const float* rec    = (const float*)d_in[4];
    const float* bias   = (const float*)d_in[5];
    const float* Wd     = (const float*)d_in[6];
    const float* bd     = (const float*)d_in[7];
    float* out = (float*)d_out;

    void *p_xz, *p_a3x, *p_a3h, *p_b3k, *p_b3w;
    cudaGetSymbolAddress(&p_xz, g_xz);
    cudaGetSymbolAddress(&p_a3x, g_a3x);
    cudaGetSymbolAddress(&p_a3h, g_a3h);
    cudaGetSymbolAddress(&p_b3k, g_b3k);
    cudaGetSymbolAddress(&p_b3w, g_b3w);

    static bool attr_done = false;
    if (!attr_done) {
        cudaFuncSetAttribute(lstm_scan_mma,
                             cudaFuncAttributeMaxDynamicSharedMemorySize, SCANSM);
        cudaFuncSetAttribute(mma_gemm,
                             cudaFuncAttributeMaxDynamicSharedMemorySize, MMASM);
        attr_done = true;
    }

    // 1) state init + operand splits
    init_state<<<(BB * UU) / 256, 256>>>(h0);
    split_pack_rows<<<(size_t)MM * DD / 256, 256>>>(x, (bf16*)p_a3x, DD);
    split_pack_T<<<((size_t)DD * GG + 255) / 256, 256>>>(kernel, (bf16*)p_b3k, DD, GG);
    split_pack_T<<<((size_t)UU * OO + 255) / 256, 256>>>(Wd, (bf16*)p_b3w, UU, OO);

    // 2) xz = x @ kernel + bias  (HMMA split-bf16; M=65536, N=4096, K3=1536)
    {
        dim3 grid(GG / 128, MM / 128);
        mma_gemm<<<grid, 256, MMASM>>>((const bf16*)p_a3x, (const bf16*)p_b3k,
                                       bias, (float*)p_xz, 3 * DD, GG);
    }

    // 3) persistent MMA LSTM scan (dataflow-synced, writes g_a3h directly)
    lstm_scan_mma<<<NBLK, 256, SCANSM>>>(rec, c0in);

    // 4) out = hs @ Wd + bd  (M=65536, N=512, K3=3072) — A3 comes from the scan
    {
        dim3 grid(OO / 128, MM / 128);
        mma_gemm<<<grid, 256, MMASM>>>((const bf16*)p_a3h, (const bf16*)p_b3w,
                                       bd, out, 3 * UU, OO);
    }
}

// round 8
// speedup vs baseline: 1.3370x; 1.3370x over previous
#include <cuda_runtime.h>
#include <cuda_bf16.h>
#include <cuda_fp16.h>
#include <cstddef>
#include <cstdint>

// Problem dims (fixed by the benchmark)
#define BB 128
#define TT 512
#define DD 512
#define UU 1024
#define GG 4096   // 4*U
#define OO 512
#define MM (BB * TT)   // 65536

#define NBLK 128        // persistent CTAs for scan

typedef __nv_bfloat16 bf16;

// ---------------- scratch (static device globals; no runtime allocation) ----
__device__ float g_xz[(size_t)MM * GG];        // [B*T][4U]
__device__ unsigned g_bar;                     // grid barrier counter

// split-bf16 K-tripled operands:  A3=[Ah|Ah|Al], B3=[Bh|Bl|Bh]
__device__ bf16 g_a3x[(size_t)MM * 3 * DD];    // x        -> [M][1536]
__device__ bf16 g_a3h[(size_t)MM * 3 * UU];    // h states -> [M][3072] (written by scan)
__device__ bf16 g_b3k[(size_t)GG * 3 * DD];    // kernel^T -> [4096][1536]
__device__ bf16 g_b3w[(size_t)OO * 3 * UU];    // Wd^T     -> [512][3072]
__device__ __half g_hf[(size_t)(TT + 1) * BB * UU];  // fp16 h history; slot 0 = h0

// ---------------- helpers ----------------------------------------------------
__device__ __forceinline__ float sigmoidf_(float x) { return 1.0f / (1.0f + __expf(-x)); }

__device__ __forceinline__ void cp16s(uint32_t daddr, const void* g) {
    asm volatile("cp.async.cg.shared.global [%0], [%1], 16;" :: "r"(daddr), "l"(g));
}
#define CP_COMMIT()  asm volatile("cp.async.commit_group;")
#define CP_WAIT(N)   asm volatile("cp.async.wait_group %0;" :: "n"(N))

__device__ __forceinline__ void ldsm_x4(uint32_t &r0, uint32_t &r1,
                                        uint32_t &r2, uint32_t &r3, uint32_t a) {
    asm volatile("ldmatrix.sync.aligned.m8n8.x4.shared.b16 {%0,%1,%2,%3}, [%4];"
                 : "=r"(r0), "=r"(r1), "=r"(r2), "=r"(r3) : "r"(a));
}
__device__ __forceinline__ void mma16816(float* d, const uint32_t* a,
                                         const uint32_t* b) {
    asm volatile(
        "mma.sync.aligned.m16n8k16.row.col.f32.bf16.bf16.f32 "
        "{%0,%1,%2,%3}, {%4,%5,%6,%7}, {%8,%9}, {%0,%1,%2,%3};"
        : "+f"(d[0]), "+f"(d[1]), "+f"(d[2]), "+f"(d[3])
        : "r"(a[0]), "r"(a[1]), "r"(a[2]), "r"(a[3]), "r"(b[0]), "r"(b[1]));
}
__device__ __forceinline__ void mma16816h(float* d, const uint32_t* a,
                                          const uint32_t* b) {
    asm volatile(
        "mma.sync.aligned.m16n8k16.row.col.f32.f16.f16.f32 "
        "{%0,%1,%2,%3}, {%4,%5,%6,%7}, {%8,%9}, {%0,%1,%2,%3};"
        : "+f"(d[0]), "+f"(d[1]), "+f"(d[2]), "+f"(d[3])
        : "r"(a[0]), "r"(a[1]), "r"(a[2]), "r"(a[3]), "r"(b[0]), "r"(b[1]));
}
__device__ __forceinline__ uint32_t swz(uint32_t o) { return o ^ ((o >> 3) & 0x70); }
__device__ __forceinline__ uint32_t packbf(bf16 a, bf16 b) {
    uint16_t x = *(uint16_t*)&a, y = *(uint16_t*)&b;
    return (uint32_t)x | ((uint32_t)y << 16);
}
__device__ __forceinline__ uint32_t packhf(__half a, __half b) {
    uint16_t x = *(uint16_t*)&a, y = *(uint16_t*)&b;
    return (uint32_t)x | ((uint32_t)y << 16);
}

// ---------------- prep kernels ----------------------------------------------
__global__ __launch_bounds__(256) void init_state(const float* __restrict__ h0) {
    int i = blockIdx.x * 256 + threadIdx.x;   // covers 128*1024
    g_hf[i] = __float2half_rn(h0[i]);          // slot 0 = h0
    if (i == 0) g_bar = 0u;
}

// in [M][K] fp32 -> out [M][3K] bf16: [Ah | Ah | Al]
__global__ __launch_bounds__(256) void split_pack_rows(
    const float* __restrict__ in, bf16* __restrict__ out, int K) {
    size_t i = (size_t)blockIdx.x * 256 + threadIdx.x;
    int m = (int)(i / K), k = (int)(i % K);
    float v = in[i];
    bf16 h = __float2bfloat16(v);
    bf16 l = __float2bfloat16(v - __bfloat162float(h));
    bf16* o = out + (size_t)m * 3 * K;
    o[k] = h; o[K + k] = h; o[2 * K + k] = l;
}

// in [K][N] fp32 -> out [N][3K] bf16: [Bh | Bl | Bh]
__global__ __launch_bounds__(256) void split_pack_T(
    const float* __restrict__ in, bf16* __restrict__ out, int K, int N) {
    size_t i = (size_t)blockIdx.x * 256 + threadIdx.x;
    if (i >= (size_t)K * N) return;
    int k = (int)(i / N), n = (int)(i % N);
    float v = in[i];
    bf16 h = __float2bfloat16(v);
    bf16 l = __float2bfloat16(v - __bfloat162float(h));
    bf16* o = out + (size_t)n * 3 * K;
    o[k] = h; o[K + k] = l; o[2 * K + k] = h;
}

// ---------------- mma.sync bf16 GEMM (best-known two-stage config) ----------
#define MMASM (2 * 32768)

__global__ __launch_bounds__(256, 1) void mma_gemm(
    const bf16* __restrict__ A3, const bf16* __restrict__ B3,
    const float* __restrict__ bias, float* __restrict__ C, int K3, int N) {
    extern __shared__ char smc[];
    const uint32_t sbase = (uint32_t)__cvta_generic_to_shared(smc);
    const int tid = threadIdx.x;
    const int wid = tid >> 5, lid = tid & 31;
    const int n0 = blockIdx.x * 128;
    const int m0 = blockIdx.y * 128;
    const int wm = (wid & 1) * 64;
    const int wn = (wid >> 1) * 32;
    const int nch = K3 / 64;

    float d[4][4][4];
#pragma unroll
    for (int i = 0; i < 4; i++)
#pragma unroll
        for (int j = 0; j < 4; j++)
#pragma unroll
            for (int q = 0; q < 4; q++) d[i][j][q] = 0.0f;

    auto load_chunk = [&](int buf, int k0) {
        uint32_t ab = sbase + buf * 32768;
        uint32_t bb = ab + 16384;
#pragma unroll
        for (int i = 0; i < 4; i++) {
            int e = tid + i * 256;
            int rr = e >> 3, c8 = e & 7;
            uint32_t off = swz((uint32_t)(rr * 128 + c8 * 16));
            cp16s(ab + off, A3 + (size_t)(m0 + rr) * K3 + k0 + c8 * 8);
            cp16s(bb + off, B3 + (size_t)(n0 + rr) * K3 + k0 + c8 * 8);
        }
    };

    load_chunk(0, 0);
    CP_COMMIT();

    int buf = 0;
    for (int c = 0; c < nch; c++) {
        if (c + 1 < nch) {
            load_chunk(buf ^ 1, (c + 1) * 64);
            CP_COMMIT();
            CP_WAIT(1);
        } else {
            CP_WAIT(0);
        }
        __syncthreads();

        const uint32_t ab = sbase + buf * 32768;
        const uint32_t bb = ab + 16384;
#pragma unroll
        for (int kk = 0; kk < 64; kk += 16) {
            uint32_t af[4][4];
#pragma unroll
            for (int mi = 0; mi < 4; mi++) {
                uint32_t off = (uint32_t)((wm + mi * 16 + (lid & 15)) * 128
                                          + kk * 2 + (lid >> 4) * 16);
                ldsm_x4(af[mi][0], af[mi][1], af[mi][2], af[mi][3], ab + swz(off));
            }
            uint32_t bf_[4][2];
#pragma unroll
            for (int ni = 0; ni < 2; ni++) {
                int sub = lid >> 3;
                uint32_t off = (uint32_t)((wn + ni * 16 + ((sub >> 1) & 1) * 8
                                           + (lid & 7)) * 128
                                          + kk * 2 + (sub & 1) * 16);
                ldsm_x4(bf_[ni * 2][0], bf_[ni * 2][1],
                        bf_[ni * 2 + 1][0], bf_[ni * 2 + 1][1], bb + swz(off));
            }
#pragma unroll
            for (int mi = 0; mi < 4; mi++)
#pragma unroll
                for (int nf = 0; nf < 4; nf++)
                    mma16816(d[mi][nf], af[mi], bf_[nf]);
        }
        __syncthreads();
        buf ^= 1;
    }

    const int lr = lid >> 2;
    const int lc = (lid & 3) * 2;
#pragma unroll
    for (int mi = 0; mi < 4; mi++) {
#pragma unroll
        for (int nf = 0; nf < 4; nf++) {
            int col = n0 + wn + nf * 8 + lc;
            float b0 = bias[col], b1 = bias[col + 1];
            int row0 = m0 + wm + mi * 16 + lr;
            float2 v0 = make_float2(d[mi][nf][0] + b0, d[mi][nf][1] + b1);
            float2 v1 = make_float2(d[mi][nf][2] + b0, d[mi][nf][3] + b1);
            *(float2*)&C[(size_t)row0 * N + col] = v0;
            *(float2*)&C[(size_t)(row0 + 8) * N + col] = v1;
        }
    }
}

// ---------------- persistent MMA LSTM scan (fp16 2-term) ---------------------
// 128 CTAs. CTA bx owns hidden cols [8bx,8bx+8) x 4 gates (N=32, col n=gate*8+j).
// R slice resident in smem as split-fp16 (Rh+Rl). h in (-1,1) -> single fp16 A.
// Per step: z = xz + hq@Rh + hq@Rl  (fp32 accum). 2 MMA terms instead of 3.
// h_t written as fp16 (next step A, g_hf[t+1]) AND bf16 [hi|hi|lo] (g_a3h, for
// the projection GEMM). c lives in registers. Grid barrier per step.
#define SC_RH 0
#define SC_RL 65536
#define SC_A  131072
#define SCANSM (SC_A + 2 * 16384)   // 163840

__global__ __launch_bounds__(256, 1) void lstm_scan_mma(
    const float* __restrict__ R, const float* __restrict__ c0in) {
    extern __shared__ char smc[];
    const uint32_t sb = (uint32_t)__cvta_generic_to_shared(smc);
    const int tid = threadIdx.x;
    const int wid = tid >> 5, lid = tid & 31;
    const int u0 = blockIdx.x * 8;
    const int wm = wid * 16;

    // ---- one-time: R slice -> smem split-fp16, swizzled chunks ----
    for (int e = tid; e < 32 * UU; e += 256) {
        int n = e & 31, k = e >> 5;
        int gate = n >> 3, j = n & 7;
        float v = R[(size_t)k * GG + gate * UU + u0 + j];
        __half h = __float2half_rn(v);
        __half l = __float2half_rn(v - __half2float(h));
        uint32_t off = (uint32_t)((k >> 6) * 4096) + swz((uint32_t)(n * 128 + (k & 63) * 2));
        *(__half*)(smc + SC_RH + off) = h;
        *(__half*)(smc + SC_RL + off) = l;
    }

    // thread's (b,u) combos — fixed for the whole scan
    const int lr = lid >> 2, lc = (lid & 3) * 2;
    const int b1 = wm + lr, b2 = b1 + 8;
    const int bs_[4] = {b1, b1, b2, b2};
    const int uj_[4] = {lc, lc + 1, lc, lc + 1};

    float creg[4];
#pragma unroll
    for (int i = 0; i < 4; i++)
        creg[i] = c0in[(size_t)bs_[i] * UU + u0 + uj_[i]];

    __syncthreads();

    for (int t = 0; t < TT; t++) {
        const __half* abase = g_hf + (size_t)t * BB * UU;   // h_{t-1} (slot t)

        auto loadA = [&](int buf, int ck) {
            uint32_t ah = sb + SC_A + buf * 16384;
#pragma unroll
            for (int i = 0; i < 4; i++) {
                int e = tid + i * 256;              // 0..1023 (16KB / 16B)
                int rr = e >> 3, c8 = e & 7;
                uint32_t off = swz((uint32_t)(rr * 128 + c8 * 16));
                cp16s(ah + off, abase + (size_t)rr * UU + ck * 64 + c8 * 8);
            }
        };

        loadA(0, 0);
        CP_COMMIT();

        // prefetch xz for this step (16 scattered LDG, hidden under MMA)
        float xzv[4][4];
#pragma unroll
        for (int i = 0; i < 4; i++) {
            const float* p = &g_xz[((size_t)bs_[i] * TT + t) * GG + u0 + uj_[i]];
#pragma unroll
            for (int g = 0; g < 4; g++) xzv[i][g] = p[(size_t)g * UU];
        }

        float d[4][4];
#pragma unroll
        for (int f = 0; f < 4; f++)
#pragma unroll
            for (int q = 0; q < 4; q++) d[f][q] = 0.0f;

        int buf = 0;
        for (int ck = 0; ck < 16; ck++) {
            if (ck + 1 < 16) {
                loadA(buf ^ 1, ck + 1);
                CP_COMMIT();
                CP_WAIT(1);
            } else {
                CP_WAIT(0);
            }
            __syncthreads();

            const uint32_t ah = sb + SC_A + buf * 16384;
            const uint32_t rh = sb + SC_RH + ck * 4096;
            const uint32_t rl = sb + SC_RL + ck * 4096;
#pragma unroll
            for (int kk = 0; kk < 64; kk += 16) {
                uint32_t offA = swz((uint32_t)((wm + (lid & 15)) * 128
                                               + kk * 2 + (lid >> 4) * 16));
                uint32_t af[4];
                ldsm_x4(af[0], af[1], af[2], af[3], ah + offA);

                uint32_t bh[4][2], bl[4][2];
#pragma unroll
                for (int ni = 0; ni < 2; ni++) {
                    int sub = lid >> 3;
                    uint32_t offB = swz((uint32_t)((ni * 16 + ((sub >> 1) & 1) * 8
                                                    + (lid & 7)) * 128
                                                   + kk * 2 + (sub & 1) * 16));
                    ldsm_x4(bh[ni * 2][0], bh[ni * 2][1],
                            bh[ni * 2 + 1][0], bh[ni * 2 + 1][1], rh + offB);
                    ldsm_x4(bl[ni * 2][0], bl[ni * 2][1],
                            bl[ni * 2 + 1][0], bl[ni * 2 + 1][1], rl + offB);
                }
#pragma unroll
                for (int f = 0; f < 4; f++) {
                    mma16816h(d[f], af, bh[f]);
                    mma16816h(d[f], af, bl[f]);
                }
            }
            __syncthreads();
            buf ^= 1;
        }

        // gate update: d[f][i] = gate f for combo i  (col n = f*8 + j)
        float hn[4];
#pragma unroll
        for (int i = 0; i < 4; i++) {
            float zi = d[0][i] + xzv[i][0];
            float zf = d[1][i] + xzv[i][1];
            float zg = d[2][i] + xzv[i][2];
            float zo = d[3][i] + xzv[i][3];
            float ig = sigmoidf_(zi);
            float fg = sigmoidf_(zf);
            float og = sigmoidf_(zo);
            float gg = tanhf(zg);
            float cn = fg * creg[i] + ig * gg;
            creg[i] = cn;
            hn[i] = og * tanhf(cn);
        }

        // write h_t: fp16 (scan A for t+1) + bf16 [hi|hi|lo] (projection A3)
#pragma unroll
        for (int pp = 0; pp < 2; pp++) {
            int b = pp ? b2 : b1;
            float v0 = hn[pp * 2], v1 = hn[pp * 2 + 1];
            // fp16 for next step
            uint32_t hfp = packhf(__float2half_rn(v0), __float2half_rn(v1));
            *(uint32_t*)&g_hf[((size_t)(t + 1) * BB + b) * UU + u0 + lc] = hfp;
            // bf16 split for projection
            bf16 h0b = __float2bfloat16(v0);
            bf16 h1b = __float2bfloat16(v1);
            bf16 l0b = __float2bfloat16(v0 - __bfloat162float(h0b));
            bf16 l1b = __float2bfloat16(v1 - __bfloat162float(h1b));
            uint32_t hp = packbf(h0b, h1b), lp = packbf(l0b, l1b);
            bf16* rowp = g_a3h + ((size_t)b * TT + t) * 3 * UU + u0 + lc;
            *(uint32_t*)(rowp)          = hp;
            *(uint32_t*)(rowp + UU)     = hp;
            *(uint32_t*)(rowp + 2 * UU) = lp;
        }

        // grid barrier
        __syncthreads();
        if (tid == 0) {
            __threadfence();
            atomicAdd(&g_bar, 1u);
            unsigned target = (unsigned)(t + 1) * NBLK;
            unsigned v;
            do {
                asm volatile("ld.global.acquire.gpu.u32 %0, [%1];"
                             : "=r"(v) : "l"(&g_bar) : "memory");
                if (v < target) __nanosleep(32);
            } while (v < target);
        }
        __syncthreads();
    }
}

// ---------------- host launcher --------------------------------------------
extern "C" void kernel_launch(void* const* d_in, const int* in_sizes, int n_in,
                              void* d_out, int out_size) {
    const float* x      = (const float*)d_in[0];
    const float* h0     = (const float*)d_in[1];
    const float* c0in   = (const float*)d_in[2];
    const float* kernel = (const float*)d_in[3];
    const float* rec    = (const float*)d_in[4];
    const float* bias   = (const float*)d_in[5];
    const float* Wd     = (const float*)d_in[6];
    const float* bd     = (const float*)d_in[7];
    float* out = (float*)d_out;

    void *p_xz, *p_a3x, *p_a3h, *p_b3k, *p_b3w;
    cudaGetSymbolAddress(&p_xz, g_xz);
    cudaGetSymbolAddress(&p_a3x, g_a3x);
    cudaGetSymbolAddress(&p_a3h, g_a3h);
    cudaGetSymbolAddress(&p_b3k, g_b3k);
    cudaGetSymbolAddress(&p_b3w, g_b3w);

    static bool attr_done = false;
    if (!attr_done) {
        cudaFuncSetAttribute(lstm_scan_mma,
                             cudaFuncAttributeMaxDynamicSharedMemorySize, SCANSM);
        cudaFuncSetAttribute(mma_gemm,
                             cudaFuncAttributeMaxDynamicSharedMemorySize, MMASM);
        attr_done = true;
    }

    // 1) state init + operand splits
    init_state<<<(BB * UU) / 256, 256>>>(h0);
    split_pack_rows<<<(size_t)MM * DD / 256, 256>>>(x, (bf16*)p_a3x, DD);
    split_pack_T<<<((size_t)DD * GG + 255) / 256, 256>>>(kernel, (bf16*)p_b3k, DD, GG);
    split_pack_T<<<((size_t)UU * OO + 255) / 256, 256>>>(Wd, (bf16*)p_b3w, UU, OO);

    // 2) xz = x @ kernel + bias  (HMMA split-bf16; M=65536, N=4096, K3=1536)
    {
        dim3 grid(GG / 128, MM / 128);
        mma_gemm<<<grid, 256, MMASM>>>((const bf16*)p_a3x, (const bf16*)p_b3k,
                                       bias, (float*)p_xz, 3 * DD, GG);
    }

    // 3) persistent MMA LSTM scan (fp16 2-term, writes g_hf + g_a3h)
    lstm_scan_mma<<<NBLK, 256, SCANSM>>>(rec, c0in);

    // 4) out = hs @ Wd + bd  (M=65536, N=512, K3=3072) — A3 comes from the scan
    {
        dim3 grid(OO / 128, MM / 128);
        mma_gemm<<<grid, 256, MMASM>>>((const bf16*)p_a3h, (const bf16*)p_b3w,
                                       bd, out, 3 * UU, OO);
    }
}

// round 9
// speedup vs baseline: 1.5316x; 1.1456x over previous
#include <cuda_runtime.h>
#include <cuda_bf16.h>
#include <cuda_fp16.h>
#include <cstddef>
#include <cstdint>

// Problem dims (fixed by the benchmark)
#define BB 128
#define TT 512
#define DD 512
#define UU 1024
#define GG 4096   // 4*U
#define OO 512
#define MM (BB * TT)   // 65536

#define NBLK 128        // persistent CTAs for scan

// ---------------- scratch (static device globals; no runtime allocation) ----
__device__ float g_xz[(size_t)MM * GG];        // [B*T][4U]
__device__ unsigned g_bar;                     // grid barrier counter

__device__ __half g_a2x[(size_t)MM * 2 * DD];  // x  -> [M][1024] = [xh|xl]
__device__ __half g_b2k[(size_t)GG * 2 * DD];  // kernel^T -> [4096][1024] = [kh|kh]
__device__ __half g_b3w[(size_t)OO * 3 * UU];  // Wd^T -> [512][3072] = [Wh|Wl|Wh]
__device__ __half g_hf[(size_t)(TT + 1) * BB * UU];  // fp16 h (hi); slot 0 = h0
__device__ __half g_hl[(size_t)(TT + 1) * BB * UU];  // fp16 h residual (lo)

// ---------------- helpers ----------------------------------------------------
__device__ __forceinline__ float sigmoidf_(float x) { return 1.0f / (1.0f + __expf(-x)); }

__device__ __forceinline__ void cp16s(uint32_t daddr, const void* g) {
    asm volatile("cp.async.cg.shared.global [%0], [%1], 16;" :: "r"(daddr), "l"(g));
}
#define CP_COMMIT()  asm volatile("cp.async.commit_group;")
#define CP_WAIT(N)   asm volatile("cp.async.wait_group %0;" :: "n"(N))

__device__ __forceinline__ void ldsm_x4(uint32_t &r0, uint32_t &r1,
                                        uint32_t &r2, uint32_t &r3, uint32_t a) {
    asm volatile("ldmatrix.sync.aligned.m8n8.x4.shared.b16 {%0,%1,%2,%3}, [%4];"
                 : "=r"(r0), "=r"(r1), "=r"(r2), "=r"(r3) : "r"(a));
}
__device__ __forceinline__ void mma16816h(float* d, const uint32_t* a,
                                          const uint32_t* b) {
    asm volatile(
        "mma.sync.aligned.m16n8k16.row.col.f32.f16.f16.f32 "
        "{%0,%1,%2,%3}, {%4,%5,%6,%7}, {%8,%9}, {%0,%1,%2,%3};"
        : "+f"(d[0]), "+f"(d[1]), "+f"(d[2]), "+f"(d[3])
        : "r"(a[0]), "r"(a[1]), "r"(a[2]), "r"(a[3]), "r"(b[0]), "r"(b[1]));
}
__device__ __forceinline__ uint32_t swz(uint32_t o) { return o ^ ((o >> 3) & 0x70); }
__device__ __forceinline__ uint32_t packhf(__half a, __half b) {
    uint16_t x = *(uint16_t*)&a, y = *(uint16_t*)&b;
    return (uint32_t)x | ((uint32_t)y << 16);
}

// ---------------- prep kernels ----------------------------------------------
__global__ __launch_bounds__(256) void init_state(const float* __restrict__ h0) {
    int i = blockIdx.x * 256 + threadIdx.x;   // covers 128*1024
    float v = h0[i];
    __half h = __float2half_rn(v);
    g_hf[i] = h;                               // slot 0 = h0
    g_hl[i] = __float2half_rn(v - __half2float(h));
    if (i == 0) g_bar = 0u;
}

// x [M][512] fp32 -> g_a2x [M][1024] fp16 [xh|xl]
__global__ __launch_bounds__(256) void split_x(const float* __restrict__ in) {
    size_t i = (size_t)blockIdx.x * 256 + threadIdx.x;   // M*DD
    int m = (int)(i / DD), k = (int)(i % DD);
    float v = in[i];
    __half h = __float2half_rn(v);
    __half l = __float2half_rn(v - __half2float(h));
    __half* o = g_a2x + (size_t)m * 2 * DD;
    o[k] = h; o[DD + k] = l;
}

// kernel [512][4096] fp32 -> g_b2k [4096][1024] fp16 [kh|kh]
__global__ __launch_bounds__(256) void split_k(const float* __restrict__ in) {
    size_t i = (size_t)blockIdx.x * 256 + threadIdx.x;   // DD*GG
    int k = (int)(i / GG), n = (int)(i % GG);
    __half h = __float2half_rn(in[i]);
    __half* o = g_b2k + (size_t)n * 2 * DD;
    o[k] = h; o[DD + k] = h;
}

// Wd [1024][512] fp32 -> g_b3w [512][3072] fp16 [Wh|Wl|Wh]
__global__ __launch_bounds__(256) void split_w(const float* __restrict__ in) {
    size_t i = (size_t)blockIdx.x * 256 + threadIdx.x;   // UU*OO
    int k = (int)(i / OO), n = (int)(i % OO);
    float v = in[i];
    __half h = __float2half_rn(v);
    __half l = __float2half_rn(v - __half2float(h));
    __half* o = g_b3w + (size_t)n * 3 * UU;
    o[k] = h; o[UU + k] = l; o[2 * UU + k] = h;
}

// ---------------- mma.sync fp16 GEMM (two-stage; used for xz) ---------------
#define MMASM (2 * 32768)

__global__ __launch_bounds__(256, 1) void mma_gemm(
    const __half* __restrict__ A2, const __half* __restrict__ B2,
    const float* __restrict__ bias, float* __restrict__ C, int K2, int N) {
    extern __shared__ char smc[];
    const uint32_t sbase = (uint32_t)__cvta_generic_to_shared(smc);
    const int tid = threadIdx.x;
    const int wid = tid >> 5, lid = tid & 31;
    const int n0 = blockIdx.x * 128;
    const int m0 = blockIdx.y * 128;
    const int wm = (wid & 1) * 64;
    const int wn = (wid >> 1) * 32;
    const int nch = K2 / 64;

    float d[4][4][4];
#pragma unroll
    for (int i = 0; i < 4; i++)
#pragma unroll
        for (int j = 0; j < 4; j++)
#pragma unroll
            for (int q = 0; q < 4; q++) d[i][j][q] = 0.0f;

    auto load_chunk = [&](int buf, int k0) {
        uint32_t ab = sbase + buf * 32768;
        uint32_t bb = ab + 16384;
#pragma unroll
        for (int i = 0; i < 4; i++) {
            int e = tid + i * 256;
            int rr = e >> 3, c8 = e & 7;
            uint32_t off = swz((uint32_t)(rr * 128 + c8 * 16));
            cp16s(ab + off, A2 + (size_t)(m0 + rr) * K2 + k0 + c8 * 8);
            cp16s(bb + off, B2 + (size_t)(n0 + rr) * K2 + k0 + c8 * 8);
        }
    };

    load_chunk(0, 0);
    CP_COMMIT();

    int buf = 0;
    for (int c = 0; c < nch; c++) {
        if (c + 1 < nch) {
            load_chunk(buf ^ 1, (c + 1) * 64);
            CP_COMMIT();
            CP_WAIT(1);
        } else {
            CP_WAIT(0);
        }
        __syncthreads();

        const uint32_t ab = sbase + buf * 32768;
        const uint32_t bb = ab + 16384;
#pragma unroll
        for (int kk = 0; kk < 64; kk += 16) {
            uint32_t af[4][4];
#pragma unroll
            for (int mi = 0; mi < 4; mi++) {
                uint32_t off = (uint32_t)((wm + mi * 16 + (lid & 15)) * 128
                                          + kk * 2 + (lid >> 4) * 16);
                ldsm_x4(af[mi][0], af[mi][1], af[mi][2], af[mi][3], ab + swz(off));
            }
            uint32_t bf_[4][2];
#pragma unroll
            for (int ni = 0; ni < 2; ni++) {
                int sub = lid >> 3;
                uint32_t off = (uint32_t)((wn + ni * 16 + ((sub >> 1) & 1) * 8
                                           + (lid & 7)) * 128
                                          + kk * 2 + (sub & 1) * 16);
                ldsm_x4(bf_[ni * 2][0], bf_[ni * 2][1],
                        bf_[ni * 2 + 1][0], bf_[ni * 2 + 1][1], bb + swz(off));
            }
#pragma unroll
            for (int mi = 0; mi < 4; mi++)
#pragma unroll
                for (int nf = 0; nf < 4; nf++)
                    mma16816h(d[mi][nf], af[mi], bf_[nf]);
        }
        __syncthreads();
        buf ^= 1;
    }

    const int lr = lid >> 2;
    const int lc = (lid & 3) * 2;
#pragma unroll
    for (int mi = 0; mi < 4; mi++) {
#pragma unroll
        for (int nf = 0; nf < 4; nf++) {
            int col = n0 + wn + nf * 8 + lc;
            float b0 = bias[col], b1 = bias[col + 1];
            int row0 = m0 + wm + mi * 16 + lr;
            float2 v0 = make_float2(d[mi][nf][0] + b0, d[mi][nf][1] + b1);
            float2 v1 = make_float2(d[mi][nf][2] + b0, d[mi][nf][3] + b1);
            *(float2*)&C[(size_t)row0 * N + col] = v0;
            *(float2*)&C[(size_t)(row0 + 8) * N + col] = v1;
        }
    }
}

// ---------------- projection GEMM: out = hs @ Wd + bd ------------------------
// A terms [hq|hq|hl] synthesized from g_hf/g_hl with row mapping m=(b,t) ->
// slot (t+1)*BB + b. B = g_b3w [512][3072] = [Wh|Wl|Wh]. K_eff = 3072.
__global__ __launch_bounds__(256, 1) void proj_gemm(
    const __half* __restrict__ hf, const __half* __restrict__ hl,
    const __half* __restrict__ B3, const float* __restrict__ bias,
    float* __restrict__ C) {
    extern __shared__ char smc[];
    const uint32_t sbase = (uint32_t)__cvta_generic_to_shared(smc);
    const int tid = threadIdx.x;
    const int wid = tid >> 5, lid = tid & 31;
    const int n0 = blockIdx.x * 128;
    const int m0 = blockIdx.y * 128;
    const int wm = (wid & 1) * 64;
    const int wn = (wid >> 1) * 32;
    const int nch = 48;   // 3072 / 64

    float d[4][4][4];
#pragma unroll
    for (int i = 0; i < 4; i++)
#pragma unroll
        for (int j = 0; j < 4; j++)
#pragma unroll
            for (int q = 0; q < 4; q++) d[i][j][q] = 0.0f;

    auto load_chunk = [&](int buf, int ck) {
        uint32_t ab = sbase + buf * 32768;
        uint32_t bb = ab + 16384;
        const __half* asrc = (ck >= 32) ? hl : hf;
        const int kcol = (ck & 15) * 64;
#pragma unroll
        for (int i = 0; i < 4; i++) {
            int e = tid + i * 256;
            int rr = e >> 3, c8 = e & 7;
            uint32_t off = swz((uint32_t)(rr * 128 + c8 * 16));
            int m = m0 + rr;
            int b = m >> 9, t = m & 511;           // m = b*TT + t
            cp16s(ab + off, asrc + ((size_t)(t + 1) * BB + b) * UU + kcol + c8 * 8);
            cp16s(bb + off, B3 + (size_t)(n0 + rr) * 3072 + ck * 64 + c8 * 8);
        }
    };

    load_chunk(0, 0);
    CP_COMMIT();

    int buf = 0;
    for (int c = 0; c < nch; c++) {
        if (c + 1 < nch) {
            load_chunk(buf ^ 1, c + 1);
            CP_COMMIT();
            CP_WAIT(1);
        } else {
            CP_WAIT(0);
        }
        __syncthreads();

        const uint32_t ab = sbase + buf * 32768;
        const uint32_t bb = ab + 16384;
#pragma unroll
        for (int kk = 0; kk < 64; kk += 16) {
            uint32_t af[4][4];
#pragma unroll
            for (int mi = 0; mi < 4; mi++) {
                uint32_t off = (uint32_t)((wm + mi * 16 + (lid & 15)) * 128
                                          + kk * 2 + (lid >> 4) * 16);
                ldsm_x4(af[mi][0], af[mi][1], af[mi][2], af[mi][3], ab + swz(off));
            }
            uint32_t bf_[4][2];
#pragma unroll
            for (int ni = 0; ni < 2; ni++) {
                int sub = lid >> 3;
                uint32_t off = (uint32_t)((wn + ni * 16 + ((sub >> 1) & 1) * 8
                                           + (lid & 7)) * 128
                                          + kk * 2 + (sub & 1) * 16);
                ldsm_x4(bf_[ni * 2][0], bf_[ni * 2][1],
                        bf_[ni * 2 + 1][0], bf_[ni * 2 + 1][1], bb + swz(off));
            }
#pragma unroll
            for (int mi = 0; mi < 4; mi++)
#pragma unroll
                for (int nf = 0; nf < 4; nf++)
                    mma16816h(d[mi][nf], af[mi], bf_[nf]);
        }
        __syncthreads();
        buf ^= 1;
    }

    const int lr = lid >> 2;
    const int lc = (lid & 3) * 2;
#pragma unroll
    for (int mi = 0; mi < 4; mi++) {
#pragma unroll
        for (int nf = 0; nf < 4; nf++) {
            int col = n0 + wn + nf * 8 + lc;
            float b0 = bias[col], b1 = bias[col + 1];
            int row0 = m0 + wm + mi * 16 + lr;
            float2 v0 = make_float2(d[mi][nf][0] + b0, d[mi][nf][1] + b1);
            float2 v1 = make_float2(d[mi][nf][2] + b0, d[mi][nf][3] + b1);
            *(float2*)&C[(size_t)row0 * OO + col] = v0;
            *(float2*)&C[(size_t)(row0 + 8) * OO + col] = v1;
        }
    }
}

// ---------------- persistent MMA LSTM scan (fp16 2-term) ---------------------
// 128 CTAs. CTA bx owns hidden cols [8bx,8bx+8) x 4 gates (N=32, col n=gate*8+j).
// R slice resident in smem as split-fp16 (Rh+Rl). h in (-1,1) -> single fp16 A.
// Per step: z = xz + hq@Rh + hq@Rl (fp32 accum). Epilogue writes hq + hl fp16.
#define SC_RH 0
#define SC_RL 65536
#define SC_A  131072
#define SCANSM (SC_A + 2 * 16384)   // 163840

__global__ __launch_bounds__(256, 1) void lstm_scan_mma(
    const float* __restrict__ R, const float* __restrict__ c0in) {
    extern __shared__ char smc[];
    const uint32_t sb = (uint32_t)__cvta_generic_to_shared(smc);
    const int tid = threadIdx.x;
    const int wid = tid >> 5, lid = tid & 31;
    const int u0 = blockIdx.x * 8;
    const int wm = wid * 16;

    // ---- one-time: R slice -> smem split-fp16, swizzled chunks ----
    for (int e = tid; e < 32 * UU; e += 256) {
        int n = e & 31, k = e >> 5;
        int gate = n >> 3, j = n & 7;
        float v = R[(size_t)k * GG + gate * UU + u0 + j];
        __half h = __float2half_rn(v);
        __half l = __float2half_rn(v - __half2float(h));
        uint32_t off = (uint32_t)((k >> 6) * 4096) + swz((uint32_t)(n * 128 + (k & 63) * 2));
        *(__half*)(smc + SC_RH + off) = h;
        *(__half*)(smc + SC_RL + off) = l;
    }

    // thread's (b,u) combos — fixed for the whole scan
    const int lr = lid >> 2, lc = (lid & 3) * 2;
    const int b1 = wm + lr, b2 = b1 + 8;
    const int bs_[4] = {b1, b1, b2, b2};
    const int uj_[4] = {lc, lc + 1, lc, lc + 1};

    float creg[4];
#pragma unroll
    for (int i = 0; i < 4; i++)
        creg[i] = c0in[(size_t)bs_[i] * UU + u0 + uj_[i]];

    __syncthreads();

    for (int t = 0; t < TT; t++) {
        const __half* abase = g_hf + (size_t)t * BB * UU;   // h_{t-1} (slot t)

        auto loadA = [&](int buf, int ck) {
            uint32_t ah = sb + SC_A + buf * 16384;
#pragma unroll
            for (int i = 0; i < 4; i++) {
                int e = tid + i * 256;              // 0..1023 (16KB / 16B)
                int rr = e >> 3, c8 = e & 7;
                uint32_t off = swz((uint32_t)(rr * 128 + c8 * 16));
                cp16s(ah + off, abase + (size_t)rr * UU + ck * 64 + c8 * 8);
            }
        };

        loadA(0, 0);
        CP_COMMIT();

        // prefetch xz for this step (16 scattered LDG, hidden under MMA)
        float xzv[4][4];
#pragma unroll
        for (int i = 0; i < 4; i++) {
            const float* p = &g_xz[((size_t)bs_[i] * TT + t) * GG + u0 + uj_[i]];
#pragma unroll
            for (int g = 0; g < 4; g++) xzv[i][g] = p[(size_t)g * UU];
        }

        float d[4][4];
#pragma unroll
        for (int f = 0; f < 4; f++)
#pragma unroll
            for (int q = 0; q < 4; q++) d[f][q] = 0.0f;

        int buf = 0;
        for (int ck = 0; ck < 16; ck++) {
            if (ck + 1 < 16) {
                loadA(buf ^ 1, ck + 1);
                CP_COMMIT();
                CP_WAIT(1);
            } else {
                CP_WAIT(0);
            }
            __syncthreads();

            const uint32_t ah = sb + SC_A + buf * 16384;
            const uint32_t rh = sb + SC_RH + ck * 4096;
            const uint32_t rl = sb + SC_RL + ck * 4096;
#pragma unroll
            for (int kk = 0; kk < 64; kk += 16) {
                uint32_t offA = swz((uint32_t)((wm + (lid & 15)) * 128
                                               + kk * 2 + (lid >> 4) * 16));
                uint32_t af[4];
                ldsm_x4(af[0], af[1], af[2], af[3], ah + offA);

                uint32_t bh[4][2], bl[4][2];
#pragma unroll
                for (int ni = 0; ni < 2; ni++) {
                    int sub = lid >> 3;
                    uint32_t offB = swz((uint32_t)((ni * 16 + ((sub >> 1) & 1) * 8
                                                    + (lid & 7)) * 128
                                                   + kk * 2 + (sub & 1) * 16));
                    ldsm_x4(bh[ni * 2][0], bh[ni * 2][1],
                            bh[ni * 2 + 1][0], bh[ni * 2 + 1][1], rh + offB);
                    ldsm_x4(bl[ni * 2][0], bl[ni * 2][1],
                            bl[ni * 2 + 1][0], bl[ni * 2 + 1][1], rl + offB);
                }
#pragma unroll
                for (int f = 0; f < 4; f++) {
                    mma16816h(d[f], af, bh[f]);
                    mma16816h(d[f], af, bl[f]);
                }
            }
            __syncthreads();
            buf ^= 1;
        }

        // gate update: d[f][i] = gate f for combo i  (col n = f*8 + j)
        float hn[4];
#pragma unroll
        for (int i = 0; i < 4; i++) {
            float zi = d[0][i] + xzv[i][0];
            float zf = d[1][i] + xzv[i][1];
            float zg = d[2][i] + xzv[i][2];
            float zo = d[3][i] + xzv[i][3];
            float ig = sigmoidf_(zi);
            float fg = sigmoidf_(zf);
            float og = sigmoidf_(zo);
            float gg = tanhf(zg);
            float cn = fg * creg[i] + ig * gg;
            creg[i] = cn;
            hn[i] = og * tanhf(cn);
        }

        // write h_t as fp16 hi (scan A for t+1 + projection) and fp16 lo (projection)
#pragma unroll
        for (int pp = 0; pp < 2; pp++) {
            int b = pp ? b2 : b1;
            float v0 = hn[pp * 2], v1 = hn[pp * 2 + 1];
            __half q0 = __float2half_rn(v0), q1 = __float2half_rn(v1);
            __half l0 = __float2half_rn(v0 - __half2float(q0));
            __half l1 = __float2half_rn(v1 - __half2float(q1));
            size_t base = ((size_t)(t + 1) * BB + b) * UU + u0 + lc;
            *(uint32_t*)&g_hf[base] = packhf(q0, q1);
            *(uint32_t*)&g_hl[base] = packhf(l0, l1);
        }

        // grid barrier
        __syncthreads();
        if (tid == 0) {
            __threadfence();
            atomicAdd(&g_bar, 1u);
            unsigned target = (unsigned)(t + 1) * NBLK;
            unsigned v;
            do {
                asm volatile("ld.global.acquire.gpu.u32 %0, [%1];"
                             : "=r"(v) : "l"(&g_bar) : "memory");
                if (v < target) __nanosleep(32);
            } while (v < target);
        }
        __syncthreads();
    }
}

// ---------------- host launcher --------------------------------------------
extern "C" void kernel_launch(void* const* d_in, const int* in_sizes, int n_in,
                              void* d_out, int out_size) {
    const float* x      = (const float*)d_in[0];
    const float* h0     = (const float*)d_in[1];
    const float* c0in   = (const float*)d_in[2];
    const float* kernel = (const float*)d_in[3];
    const float* rec    = (const float*)d_in[4];
    const float* bias   = (const float*)d_in[5];
    const float* Wd     = (const float*)d_in[6];
    const float* bd     = (const float*)d_in[7];
    float* out = (float*)d_out;

    void *p_xz, *p_a2x, *p_b2k, *p_b3w, *p_hf, *p_hl;
    cudaGetSymbolAddress(&p_xz, g_xz);
    cudaGetSymbolAddress(&p_a2x, g_a2x);
    cudaGetSymbolAddress(&p_b2k, g_b2k);
    cudaGetSymbolAddress(&p_b3w, g_b3w);
    cudaGetSymbolAddress(&p_hf, g_hf);
    cudaGetSymbolAddress(&p_hl, g_hl);

    static bool attr_done = false;
    if (!attr_done) {
        cudaFuncSetAttribute(lstm_scan_mma,
                             cudaFuncAttributeMaxDynamicSharedMemorySize, SCANSM);
        cudaFuncSetAttribute(mma_gemm,
                             cudaFuncAttributeMaxDynamicSharedMemorySize, MMASM);
        cudaFuncSetAttribute(proj_gemm,
                             cudaFuncAttributeMaxDynamicSharedMemorySize, MMASM);
        attr_done = true;
    }

    // 1) state init + operand splits
    init_state<<<(BB * UU) / 256, 256>>>(h0);
    split_x<<<(size_t)MM * DD / 256, 256>>>(x);
    split_k<<<(size_t)DD * GG / 256, 256>>>(kernel);
    split_w<<<(size_t)UU * OO / 256, 256>>>(Wd);

    // 2) xz = x @ kernel + bias  (fp16 2-term; M=65536, N=4096, K2=1024)
    {
        dim3 grid(GG / 128, MM / 128);
        mma_gemm<<<grid, 256, MMASM>>>((const __half*)p_a2x, (const __half*)p_b2k,
                                       bias, (float*)p_xz, 2 * DD, GG);
    }

    // 3) persistent MMA LSTM scan (fp16 2-term, writes g_hf + g_hl)
    lstm_scan_mma<<<NBLK, 256, SCANSM>>>(rec, c0in);

    // 4) out = hs @ Wd + bd  (3-term fp16 from g_hf/g_hl; M=65536, N=512)
    {
        dim3 grid(OO / 128, MM / 128);
        proj_gemm<<<grid, 256, MMASM>>>((const __half*)p_hf, (const __half*)p_hl,
                                        (const __half*)p_b3w, bd, out);
    }
}